// round 12
// baseline (speedup 1.0000x reference)
#include <cuda_runtime.h>
#include <cstdint>
#include <cstring>

// Problem constants (fixed by the dataset)
#define LNUM 4
#define BNUM 16
#define NTOK 4096
#define DDIM 1024
#define KSEL 100
#define KCL  20
#define DTOT 4096   /* LNUM*DDIM */
#define PROWS 112   /* 100 padded to 112 (9 blocks * 12 points + slack) */
#define NCH   4     /* d-chunks for assign/update split */
#define CHF4  256   /* float4 per chunk (1024 floats) */
#define ITERS 10

typedef unsigned long long ull;

// ---------------------------------------------------------------------------
// Scratch (static __device__ globals; no allocation anywhere)
// ---------------------------------------------------------------------------
__device__ float g_X    [BNUM * PROWS * DTOT];       // stacked tokens [B][112][4096]
__device__ float g_xx   [BNUM * PROWS];              // |x|^2 per row (full-d)
__device__ float g_C    [BNUM * KCL * DTOT];         // centroids [B][20][4096]
__device__ float g_ccpart[BNUM * KCL * NCH];         // per-chunk partial |c|^2
__device__ float g_dot  [BNUM * PROWS * KCL * NCH];  // per-chunk partial dots
__device__ int   g_top  [BNUM * KSEL];               // top-100 token indices
__device__ float g_m    [BNUM * DDIM];               // pre-normalize centers
__device__ float g_ns   [BNUM * NCH];                // partial sum-of-squares

// floor(linspace(0,99,20)) computed exactly as jnp does it
__constant__ int c_init_idx[KCL] = {0,5,10,15,20,26,31,36,41,46,52,57,62,67,72,78,83,88,93,99};

// Packed fp32x2 ops (Blackwell sm_103a; FFMA2 only reachable via PTX)
__device__ __forceinline__ ull fma2(ull a, ull b, ull c) {
    ull d;
    asm("fma.rn.f32x2 %0, %1, %2, %3;" : "=l"(d) : "l"(a), "l"(b), "l"(c));
    return d;
}
__device__ __forceinline__ ull add2(ull a, ull b) {
    ull d;
    asm("add.rn.f32x2 %0, %1, %2;" : "=l"(d) : "l"(a), "l"(b));
    return d;
}

// ---------------------------------------------------------------------------
// Kernel 1: anomaly score + stable top-100 (bitonic sort). Unchanged (passing).
// ---------------------------------------------------------------------------
__global__ __launch_bounds__(1024) void k_topk(const float* __restrict__ anom) {
    const int b = blockIdx.x;
    const int tid = threadIdx.x;
    __shared__ unsigned long long keys[NTOK];

    for (int n = tid; n < NTOK; n += 1024) {
        float s0 = 0.f, s1 = 0.f;
#pragma unroll
        for (int l = 0; l < LNUM; ++l) {
            const float2 v = reinterpret_cast<const float2*>(anom)[(size_t)(l * BNUM + b) * NTOK + n];
            s0 += v.x;
            s1 += v.y;
        }
        const float m0 = s0 * 0.25f;
        const float m1 = s1 * 0.25f;
        const float mx = fmaxf(m0, m1);
        const float e0 = expf(m0 - mx);
        const float e1 = expf(m1 - mx);
        const float sc = __fdiv_rn(e1, e0 + e1);
        unsigned u = __float_as_uint(sc);
        u = (u & 0x80000000u) ? ~u : (u | 0x80000000u);
        keys[n] = ((unsigned long long)(~u) << 32) | (unsigned)n;
    }

    for (int kk = 2; kk <= NTOK; kk <<= 1) {
        for (int j = kk >> 1; j > 0; j >>= 1) {
            __syncthreads();
            for (int t = tid; t < NTOK; t += 1024) {
                const int ixj = t ^ j;
                if (ixj > t) {
                    const unsigned long long A = keys[t];
                    const unsigned long long Bv = keys[ixj];
                    const bool up = ((t & kk) == 0);
                    if ((A > Bv) == up) { keys[t] = Bv; keys[ixj] = A; }
                }
            }
        }
    }
    __syncthreads();
    if (tid < KSEL) g_top[b * KSEL + tid] = (int)(keys[tid] & 0xFFFFu);
}

// ---------------------------------------------------------------------------
// Kernel 2: gather top tokens + xx, with centroid init FUSED in.
// For init rows (j in c_init_idx) also writes g_C and per-chunk ccpart using
// exactly k_init's fmaf nesting + 128-thread tree (bitwise identical to the
// previous separate k_init). Grid (112, 16), 128 threads.
// ---------------------------------------------------------------------------
__global__ __launch_bounds__(128) void k_gather(const float* __restrict__ pt) {
    const int j = blockIdx.x;
    const int b = blockIdx.y;
    const int tid = threadIdx.x;
    float* dst = g_X + ((size_t)b * PROWS + j) * DTOT;
    float sq = 0.f;
    __shared__ float red[128];

    bool isInit = false;
    int kc = 0;
    if (j < KSEL) {
#pragma unroll
        for (int k = 0; k < KCL; ++k)
            if (c_init_idx[k] == j) { isInit = true; kc = k; }
    }

    if (j < KSEL) {
        const int idx = g_top[b * KSEL + j];
#pragma unroll
        for (int l = 0; l < LNUM; ++l) {
            const float4* src = reinterpret_cast<const float4*>(
                pt + (((size_t)l * BNUM + b) * NTOK + idx) * DDIM);
            float4* d4 = reinterpret_cast<float4*>(dst + l * DDIM);

            const float4 v0 = src[tid];
            d4[tid] = v0;
            sq = fmaf(v0.x, v0.x, fmaf(v0.y, v0.y, fmaf(v0.z, v0.z, fmaf(v0.w, v0.w, sq))));
            const float4 v1 = src[tid + 128];
            d4[tid + 128] = v1;
            sq = fmaf(v1.x, v1.x, fmaf(v1.y, v1.y, fmaf(v1.z, v1.z, fmaf(v1.w, v1.w, sq))));

            if (isInit) {   // block-uniform branch (j is per-block)
                float4* cd = reinterpret_cast<float4*>(
                    g_C + ((size_t)b * KCL + kc) * DTOT + l * DDIM);
                cd[tid] = v0;
                cd[tid + 128] = v1;
                // exact k_init chain: v0 outer, v1 inner, innermost v1.w*v1.w
                const float sql =
                    fmaf(v0.x, v0.x, fmaf(v0.y, v0.y, fmaf(v0.z, v0.z, fmaf(v0.w, v0.w,
                    fmaf(v1.x, v1.x, fmaf(v1.y, v1.y, fmaf(v1.z, v1.z, v1.w * v1.w)))))));
                red[tid] = sql;
                __syncthreads();
                for (int s = 64; s > 0; s >>= 1) {
                    if (tid < s) red[tid] += red[tid + s];
                    __syncthreads();
                }
                if (tid == 0) g_ccpart[(b * KCL + kc) * NCH + l] = red[0];
                __syncthreads();
            }
        }
    } else {
        const float4 z = make_float4(0.f, 0.f, 0.f, 0.f);
        float4* d4 = reinterpret_cast<float4*>(dst);
#pragma unroll
        for (int u = 0; u < 8; ++u) d4[tid + u * 128] = z;
    }

    red[tid] = sq;
    __syncthreads();
    for (int s = 64; s > 0; s >>= 1) {
        if (tid < s) red[tid] += red[tid + s];
        __syncthreads();
    }
    if (tid == 0) g_xx[b * PROWS + j] = red[0];
}

// ---------------------------------------------------------------------------
// Kernel 3 (hot, x11): partial dot products, d-chunked, packed f32x2 FMA.
// Grid (9, 16, 4) = 576 blocks, 240 threads, >=3 blocks/SM pinned.
// Thread = 4-point x 4-cluster tile over a 1/16 slice of its chunk; each
// float4 becomes a ulonglong2 (two packed fp32 pairs), 32 FFMA2 per iter.
// ---------------------------------------------------------------------------
__global__ __launch_bounds__(240, 3) void k_assign_part() {
    const int b   = blockIdx.y;
    const int jb  = blockIdx.x * 12;
    const int ch  = blockIdx.z;
    const int tid = threadIdx.x;          // 0..239
    const int ds   = tid & 15;            // d-split slot (16)
    const int tile = tid >> 4;            // 0..14
    const int kg   = tile % 5;            // cluster group (4 clusters)
    const int pg   = tile / 5;            // point group (4 points)

    const ulonglong2* Xb2 = reinterpret_cast<const ulonglong2*>(g_X) +
                            (size_t)b * PROWS * (DTOT / 4);
    const ulonglong2* Cb2 = reinterpret_cast<const ulonglong2*>(g_C) +
                            (size_t)b * KCL * (DTOT / 4);

    const ulonglong2* xr[4];
    const ulonglong2* cr[4];
#pragma unroll
    for (int i = 0; i < 4; ++i)
        xr[i] = Xb2 + (size_t)(jb + pg * 4 + i) * (DTOT / 4) + ch * CHF4;
#pragma unroll
    for (int q = 0; q < 4; ++q)
        cr[q] = Cb2 + (size_t)(kg * 4 + q) * (DTOT / 4) + ch * CHF4;

    ull acc[4][4];
#pragma unroll
    for (int i = 0; i < 4; ++i)
#pragma unroll
        for (int q = 0; q < 4; ++q) acc[i][q] = 0ull;

    for (int s = 0; s < 16; ++s) {
        const int f = ds + 16 * s;        // float4 index within chunk (0..255)
        ulonglong2 xv[4], cv[4];
#pragma unroll
        for (int i = 0; i < 4; ++i) xv[i] = xr[i][f];
#pragma unroll
        for (int q = 0; q < 4; ++q) cv[q] = cr[q][f];
#pragma unroll
        for (int i = 0; i < 4; ++i)
#pragma unroll
            for (int q = 0; q < 4; ++q) {
                ull a = acc[i][q];
                a = fma2(xv[i].x, cv[q].x, a);   // (x,y) pair
                a = fma2(xv[i].y, cv[q].y, a);   // (z,w) pair
                acc[i][q] = a;
            }
    }

    __shared__ float red[240 * 17];       // padded: slot*17 + ds (conflict-free)
#pragma unroll
    for (int i = 0; i < 4; ++i)
#pragma unroll
        for (int q = 0; q < 4; ++q) {
            const int slot = (pg * 4 + i) * KCL + (kg * 4 + q);
            float2 p;
            memcpy(&p, &acc[i][q], 8);
            red[slot * 17 + ds] = p.x + p.y;
        }
    __syncthreads();

    {   // one thread per (point,cluster): deterministic fixed-order ds-sum
        const int slot = tid;             // 0..239 = 12*20
        const int p = slot / KCL;
        const int k = slot - p * KCL;
        float ssum = 0.f;
#pragma unroll
        for (int d = 0; d < 16; ++d) ssum += red[slot * 17 + d];
        g_dot[((size_t)(b * PROWS + jb + p) * KCL + k) * NCH + ch] = ssum;
    }
}

// ---------------------------------------------------------------------------
// Kernel 4 (x10): fused label + centroid update, d-chunked, packed f32x2 adds
// (per-component chains identical to scalar -> bitwise-same results).
// Grid (20, 16, 4), 128 threads.
// ---------------------------------------------------------------------------
__global__ __launch_bounds__(128) void k_update() {
    const int k  = blockIdx.x;
    const int b  = blockIdx.y;
    const int ch = blockIdx.z;
    const int tid = threadIdx.x;

    __shared__ float ccs[KCL];
    __shared__ int   labs[KSEL];
    __shared__ float red[128];

    if (tid < KCL) {
        const float4 v = reinterpret_cast<const float4*>(g_ccpart)[b * KCL + tid];
        ccs[tid] = ((v.x + v.y) + v.z) + v.w;    // fixed chunk order 0,1,2,3
    }
    __syncthreads();

    if (tid < KSEL) {
        const float xx = g_xx[b * PROWS + tid];
        const float4* dotp = reinterpret_cast<const float4*>(g_dot) +
                             (size_t)(b * PROWS + tid) * KCL;
        const float4 v0 = dotp[0];
        float bv = (xx - 2.0f * (((v0.x + v0.y) + v0.z) + v0.w)) + ccs[0];
        int best = 0;
#pragma unroll
        for (int k2 = 1; k2 < KCL; ++k2) {
            const float4 v = dotp[k2];
            const float d2 = (xx - 2.0f * (((v.x + v.y) + v.z) + v.w)) + ccs[k2];
            if (d2 < bv) { bv = d2; best = k2; }   // first-min, like jnp.argmin
        }
        labs[tid] = best;
    }
    __syncthreads();

    int cnt = 0;
    for (int j = 0; j < KSEL; ++j) cnt += (labs[j] == k);

    ulonglong2 A0, A1;
    A0.x = 0ull; A0.y = 0ull; A1.x = 0ull; A1.y = 0ull;
    const ulonglong2* Xb2 = reinterpret_cast<const ulonglong2*>(g_X) +
                            (size_t)b * PROWS * (DTOT / 4) + ch * CHF4;
    for (int j = 0; j < KSEL; ++j) {
        if (labs[j] == k) {
            const ulonglong2* row = Xb2 + (size_t)j * (DTOT / 4);
            const ulonglong2 v0 = row[tid];
            const ulonglong2 v1 = row[tid + 128];
            A0.x = add2(A0.x, v0.x);
            A0.y = add2(A0.y, v0.y);
            A1.x = add2(A1.x, v1.x);
            A1.y = add2(A1.y, v1.y);
        }
    }

    if (cnt > 0) {                         // uniform across block
        const float fc = (float)cnt;
        float2 a0xy, a0zw, a1xy, a1zw;
        memcpy(&a0xy, &A0.x, 8); memcpy(&a0zw, &A0.y, 8);
        memcpy(&a1xy, &A1.x, 8); memcpy(&a1zw, &A1.y, 8);

        float4 c0, c1;
        c0.x = __fdiv_rn(a0xy.x, fc); c0.y = __fdiv_rn(a0xy.y, fc);
        c0.z = __fdiv_rn(a0zw.x, fc); c0.w = __fdiv_rn(a0zw.y, fc);
        c1.x = __fdiv_rn(a1xy.x, fc); c1.y = __fdiv_rn(a1xy.y, fc);
        c1.z = __fdiv_rn(a1zw.x, fc); c1.w = __fdiv_rn(a1zw.y, fc);

        float4* crow = reinterpret_cast<float4*>(g_C) +
                       (size_t)(b * KCL + k) * (DTOT / 4) + ch * CHF4;
        crow[tid] = c0;
        crow[tid + 128] = c1;

        float sq = fmaf(c0.x, c0.x, fmaf(c0.y, c0.y, fmaf(c0.z, c0.z, fmaf(c0.w, c0.w,
                   fmaf(c1.x, c1.x, fmaf(c1.y, c1.y, fmaf(c1.z, c1.z, c1.w * c1.w)))))));
        red[tid] = sq;
        __syncthreads();
        for (int s = 64; s > 0; s >>= 1) {
            if (tid < s) red[tid] += red[tid + s];
            __syncthreads();
        }
        if (tid == 0) g_ccpart[(b * KCL + k) * NCH + ch] = red[0];
    }
}

// ---------------------------------------------------------------------------
// Kernel 5: final part 1, d-chunked, with final label assignment FUSED in
// (same fixed-order argmin as k_update; identical across the 4 ch blocks).
// Grid (16, 4), 64 threads. j-outer segment accumulation (ascending j, same
// as reference segment_sum). Writes g_m and per-chunk sumsq to g_ns.
// ---------------------------------------------------------------------------
__global__ __launch_bounds__(64) void k_final1() {
    const int b  = blockIdx.x;
    const int ch = blockIdx.y;
    const int tid = threadIdx.x;           // 0..63, float4 column within chunk

    __shared__ float4 seg[KCL][64];
    __shared__ int    labs[KSEL];
    __shared__ float  cnts[KCL];
    __shared__ float  red[64];
    __shared__ float  ccs[KCL];

    if (tid < KCL) {
        const float4 v = reinterpret_cast<const float4*>(g_ccpart)[b * KCL + tid];
        ccs[tid] = ((v.x + v.y) + v.z) + v.w;
    }
#pragma unroll
    for (int k = 0; k < KCL; ++k) seg[k][tid] = make_float4(0.f, 0.f, 0.f, 0.f);
    __syncthreads();

    for (int j = tid; j < KSEL; j += 64) {
        const float xx = g_xx[b * PROWS + j];
        const float4* dotp = reinterpret_cast<const float4*>(g_dot) +
                             (size_t)(b * PROWS + j) * KCL;
        const float4 v0 = dotp[0];
        float bv = (xx - 2.0f * (((v0.x + v0.y) + v0.z) + v0.w)) + ccs[0];
        int best = 0;
#pragma unroll
        for (int k2 = 1; k2 < KCL; ++k2) {
            const float4 v = dotp[k2];
            const float d2 = (xx - 2.0f * (((v.x + v.y) + v.z) + v.w)) + ccs[k2];
            if (d2 < bv) { bv = d2; best = k2; }
        }
        labs[j] = best;
    }
    __syncthreads();

    if (tid < KCL) {
        int c = 0;
        for (int j = 0; j < KSEL; ++j) c += (labs[j] == tid);
        cnts[tid] = (float)c;
    }
    __syncthreads();

    const float4* Xb4 = reinterpret_cast<const float4*>(g_X) + (size_t)b * PROWS * (DTOT / 4);
    const int fi = ch * 64 + tid;          // float4 index within a layer block (0..255)

    for (int j = 0; j < KSEL; ++j) {
        const int lab = labs[j];
        const float4* row = Xb4 + (size_t)j * (DTOT / 4);
        const float4 v0 = row[fi];
        const float4 v1 = row[256 + fi];
        const float4 v2 = row[512 + fi];
        const float4 v3 = row[768 + fi];
        float4 a;
        a.x = (((v0.x + v1.x) + v2.x) + v3.x) * 0.25f;
        a.y = (((v0.y + v1.y) + v2.y) + v3.y) * 0.25f;
        a.z = (((v0.z + v1.z) + v2.z) + v3.z) * 0.25f;
        a.w = (((v0.w + v1.w) + v2.w) + v3.w) * 0.25f;
        float4 s = seg[lab][tid];
        s.x += a.x; s.y += a.y; s.z += a.z; s.w += a.w;
        seg[lab][tid] = s;
    }
    __syncthreads();

    float mx = 0.f, my = 0.f, mz = 0.f, mw = 0.f;
#pragma unroll
    for (int k = 0; k < KCL; ++k) {
        const float fc = cnts[k];
        if (fc > 0.f) {
            const float4 s = seg[k][tid];
            mx += __fdiv_rn(s.x, fc);
            my += __fdiv_rn(s.y, fc);
            mz += __fdiv_rn(s.z, fc);
            mw += __fdiv_rn(s.w, fc);
        }
    }
    const float cx = __fdiv_rn(mx, 20.f);
    const float cy = __fdiv_rn(my, 20.f);
    const float cz = __fdiv_rn(mz, 20.f);
    const float cw = __fdiv_rn(mw, 20.f);

    float4 o; o.x = cx; o.y = cy; o.z = cz; o.w = cw;
    reinterpret_cast<float4*>(g_m)[b * 256 + fi] = o;

    red[tid] = ((cx * cx + cy * cy) + cz * cz) + cw * cw;
    __syncthreads();
    for (int s = 32; s > 0; s >>= 1) {
        if (tid < s) red[tid] += red[tid + s];
        __syncthreads();
    }
    if (tid == 0) g_ns[b * NCH + ch] = red[0];
}

// ---------------------------------------------------------------------------
// Kernel 6: final part 2 — normalize. Grid 16, 256 threads.
// ---------------------------------------------------------------------------
__global__ __launch_bounds__(256) void k_final2(float* __restrict__ out) {
    const int b = blockIdx.x;
    const int tid = threadIdx.x;           // one float4 of D=1024

    const float4 nsv = reinterpret_cast<const float4*>(g_ns)[b];
    const float ns = ((nsv.x + nsv.y) + nsv.z) + nsv.w;
    float norm = __fsqrt_rn(ns);
    norm = fmaxf(norm, 1e-12f);

    const float4 c = reinterpret_cast<const float4*>(g_m)[b * 256 + tid];
    float4 o;
    o.x = __fdiv_rn(c.x, norm);
    o.y = __fdiv_rn(c.y, norm);
    o.z = __fdiv_rn(c.z, norm);
    o.w = __fdiv_rn(c.w, norm);
    reinterpret_cast<float4*>(out)[b * 256 + tid] = o;
}

// ---------------------------------------------------------------------------
// Launch: 25-node dependent chain on the capture stream.
// ---------------------------------------------------------------------------
extern "C" void kernel_launch(void* const* d_in, const int* in_sizes, int n_in,
                              void* d_out, int out_size) {
    (void)in_sizes; (void)n_in; (void)out_size;
    const float* pt = (const float*)d_in[0];   // patch_tokens [4,16,4096,1024] f32
    const float* an = (const float*)d_in[1];   // anomaly_maps [4,16,4096,2] f32
    float* out = (float*)d_out;                // [16,1024] f32

    k_topk  <<<BNUM, 1024>>>(an);
    k_gather<<<dim3(PROWS, BNUM), 128>>>(pt);   // gather + centroid init fused
    for (int it = 0; it < ITERS; ++it) {
        k_assign_part<<<dim3(9, BNUM, NCH), 240>>>();
        k_update     <<<dim3(KCL, BNUM, NCH), 128>>>();
    }
    k_assign_part<<<dim3(9, BNUM, NCH), 240>>>();
    k_final1     <<<dim3(BNUM, NCH), 64>>>();   // final labels + segment means
    k_final2     <<<BNUM, 256>>>(out);
}

// round 14
// speedup vs baseline: 1.2440x; 1.2440x over previous
#include <cuda_runtime.h>
#include <cstdint>
#include <cstring>

// Problem constants (fixed by the dataset)
#define LNUM 4
#define BNUM 16
#define NTOK 4096
#define DDIM 1024
#define KSEL 100
#define KCL  20
#define DTOT 4096   /* LNUM*DDIM */
#define PROWS 112   /* 100 padded to 112 (9 blocks * 12 points + slack) */
#define NCH   4     /* d-chunks for assign/update split */
#define CHF4  256   /* float4 per chunk (1024 floats) */
#define ITERS 10

// ---------------------------------------------------------------------------
// Scratch (static __device__ globals; no allocation anywhere)
// ---------------------------------------------------------------------------
__device__ float g_X    [BNUM * PROWS * DTOT];       // stacked tokens [B][112][4096]
__device__ float g_xx   [BNUM * PROWS];              // |x|^2 per row (full-d)
__device__ float g_C    [BNUM * KCL * DTOT];         // centroids [B][20][4096]
__device__ float g_ccpart[BNUM * KCL * NCH];         // per-chunk partial |c|^2
__device__ float g_dot  [BNUM * PROWS * KCL * NCH];  // per-chunk partial dots
__device__ int   g_top  [BNUM * KSEL];               // top-100 token indices
__device__ float g_m    [BNUM * DDIM];               // pre-normalize centers
__device__ float g_ns   [BNUM * NCH];                // partial sum-of-squares

// floor(linspace(0,99,20)) computed exactly as jnp does it
__constant__ int c_init_idx[KCL] = {0,5,10,15,20,26,31,36,41,46,52,57,62,67,72,78,83,88,93,99};

// ---------------------------------------------------------------------------
// Kernel 1: anomaly score + stable top-100 (bitonic sort). Unchanged (passing).
// ---------------------------------------------------------------------------
__global__ __launch_bounds__(1024) void k_topk(const float* __restrict__ anom) {
    const int b = blockIdx.x;
    const int tid = threadIdx.x;
    __shared__ unsigned long long keys[NTOK];

    for (int n = tid; n < NTOK; n += 1024) {
        float s0 = 0.f, s1 = 0.f;
#pragma unroll
        for (int l = 0; l < LNUM; ++l) {
            const float2 v = reinterpret_cast<const float2*>(anom)[(size_t)(l * BNUM + b) * NTOK + n];
            s0 += v.x;
            s1 += v.y;
        }
        const float m0 = s0 * 0.25f;
        const float m1 = s1 * 0.25f;
        const float mx = fmaxf(m0, m1);
        const float e0 = expf(m0 - mx);
        const float e1 = expf(m1 - mx);
        const float sc = __fdiv_rn(e1, e0 + e1);
        unsigned u = __float_as_uint(sc);
        u = (u & 0x80000000u) ? ~u : (u | 0x80000000u);
        keys[n] = ((unsigned long long)(~u) << 32) | (unsigned)n;
    }

    for (int kk = 2; kk <= NTOK; kk <<= 1) {
        for (int j = kk >> 1; j > 0; j >>= 1) {
            __syncthreads();
            for (int t = tid; t < NTOK; t += 1024) {
                const int ixj = t ^ j;
                if (ixj > t) {
                    const unsigned long long A = keys[t];
                    const unsigned long long Bv = keys[ixj];
                    const bool up = ((t & kk) == 0);
                    if ((A > Bv) == up) { keys[t] = Bv; keys[ixj] = A; }
                }
            }
        }
    }
    __syncthreads();
    if (tid < KSEL) g_top[b * KSEL + tid] = (int)(keys[tid] & 0xFFFFu);
}

// ---------------------------------------------------------------------------
// Kernel 2: gather top tokens + xx, with centroid init FUSED in (passing R12,
// bitwise identical to separate k_init). Grid (112, 16), 128 threads.
// ---------------------------------------------------------------------------
__global__ __launch_bounds__(128) void k_gather(const float* __restrict__ pt) {
    const int j = blockIdx.x;
    const int b = blockIdx.y;
    const int tid = threadIdx.x;
    float* dst = g_X + ((size_t)b * PROWS + j) * DTOT;
    float sq = 0.f;
    __shared__ float red[128];

    bool isInit = false;
    int kc = 0;
    if (j < KSEL) {
#pragma unroll
        for (int k = 0; k < KCL; ++k)
            if (c_init_idx[k] == j) { isInit = true; kc = k; }
    }

    if (j < KSEL) {
        const int idx = g_top[b * KSEL + j];
#pragma unroll
        for (int l = 0; l < LNUM; ++l) {
            const float4* src = reinterpret_cast<const float4*>(
                pt + (((size_t)l * BNUM + b) * NTOK + idx) * DDIM);
            float4* d4 = reinterpret_cast<float4*>(dst + l * DDIM);

            const float4 v0 = src[tid];
            d4[tid] = v0;
            sq = fmaf(v0.x, v0.x, fmaf(v0.y, v0.y, fmaf(v0.z, v0.z, fmaf(v0.w, v0.w, sq))));
            const float4 v1 = src[tid + 128];
            d4[tid + 128] = v1;
            sq = fmaf(v1.x, v1.x, fmaf(v1.y, v1.y, fmaf(v1.z, v1.z, fmaf(v1.w, v1.w, sq))));

            if (isInit) {   // block-uniform branch (j is per-block)
                float4* cd = reinterpret_cast<float4*>(
                    g_C + ((size_t)b * KCL + kc) * DTOT + l * DDIM);
                cd[tid] = v0;
                cd[tid + 128] = v1;
                const float sql =
                    fmaf(v0.x, v0.x, fmaf(v0.y, v0.y, fmaf(v0.z, v0.z, fmaf(v0.w, v0.w,
                    fmaf(v1.x, v1.x, fmaf(v1.y, v1.y, fmaf(v1.z, v1.z, v1.w * v1.w)))))));
                red[tid] = sql;
                __syncthreads();
                for (int s = 64; s > 0; s >>= 1) {
                    if (tid < s) red[tid] += red[tid + s];
                    __syncthreads();
                }
                if (tid == 0) g_ccpart[(b * KCL + kc) * NCH + l] = red[0];
                __syncthreads();
            }
        }
    } else {
        const float4 z = make_float4(0.f, 0.f, 0.f, 0.f);
        float4* d4 = reinterpret_cast<float4*>(dst);
#pragma unroll
        for (int u = 0; u < 8; ++u) d4[tid + u * 128] = z;
    }

    red[tid] = sq;
    __syncthreads();
    for (int s = 64; s > 0; s >>= 1) {
        if (tid < s) red[tid] += red[tid + s];
        __syncthreads();
    }
    if (tid == 0) g_xx[b * PROWS + j] = red[0];
}

// ---------------------------------------------------------------------------
// Kernel 3 (hot, x11): partial dot products — EXACT R11 version (measured
// 16.3us, best). Grid (9, 16, 4) = 576 blocks, 240 threads, 4 blocks/SM.
// ---------------------------------------------------------------------------
__global__ __launch_bounds__(240, 4) void k_assign_part() {
    const int b   = blockIdx.y;
    const int jb  = blockIdx.x * 12;
    const int ch  = blockIdx.z;
    const int tid = threadIdx.x;          // 0..239
    const int ds   = tid & 15;            // d-split slot (16)
    const int tile = tid >> 4;            // 0..14
    const int kg   = tile % 5;            // cluster group (4 clusters)
    const int pg   = tile / 5;            // point group (4 points)

    const float4* Xb4 = reinterpret_cast<const float4*>(g_X) + (size_t)b * PROWS * (DTOT / 4);
    const float4* Cb4 = reinterpret_cast<const float4*>(g_C) + (size_t)b * KCL * (DTOT / 4);

    const float4* xr[4];
    const float4* cr[4];
#pragma unroll
    for (int i = 0; i < 4; ++i)
        xr[i] = Xb4 + (size_t)(jb + pg * 4 + i) * (DTOT / 4) + ch * CHF4;
#pragma unroll
    for (int q = 0; q < 4; ++q)
        cr[q] = Cb4 + (size_t)(kg * 4 + q) * (DTOT / 4) + ch * CHF4;

    float acc[4][4];
#pragma unroll
    for (int i = 0; i < 4; ++i)
#pragma unroll
        for (int q = 0; q < 4; ++q) acc[i][q] = 0.f;

    for (int s = 0; s < 16; ++s) {
        const int f = ds + 16 * s;        // float4 index within chunk (0..255)
        float4 xv[4], cv[4];
#pragma unroll
        for (int i = 0; i < 4; ++i) xv[i] = xr[i][f];
#pragma unroll
        for (int q = 0; q < 4; ++q) cv[q] = cr[q][f];
#pragma unroll
        for (int i = 0; i < 4; ++i)
#pragma unroll
            for (int q = 0; q < 4; ++q) {
                float a = acc[i][q];
                a = fmaf(xv[i].x, cv[q].x, a);
                a = fmaf(xv[i].y, cv[q].y, a);
                a = fmaf(xv[i].z, cv[q].z, a);
                a = fmaf(xv[i].w, cv[q].w, a);
                acc[i][q] = a;
            }
    }

    __shared__ float red[240 * 17];       // padded: slot*17 + ds (conflict-free)
#pragma unroll
    for (int i = 0; i < 4; ++i)
#pragma unroll
        for (int q = 0; q < 4; ++q) {
            const int slot = (pg * 4 + i) * KCL + (kg * 4 + q);
            red[slot * 17 + ds] = acc[i][q];
        }
    __syncthreads();

    {   // one thread per (point,cluster): deterministic fixed-order ds-sum
        const int slot = tid;             // 0..239 = 12*20
        const int p = slot / KCL;
        const int k = slot - p * KCL;
        float ssum = 0.f;
#pragma unroll
        for (int d = 0; d < 16; ++d) ssum += red[slot * 17 + d];
        g_dot[((size_t)(b * PROWS + jb + p) * KCL + k) * NCH + ch] = ssum;
    }
}

// ---------------------------------------------------------------------------
// Kernel 4 (x10): fused label + centroid update, d-chunked. 128 threads.
// ALL floating-point math is BITWISE IDENTICAL to the R11-passing version:
// same argmin expression, same a0/a1 per-component chains in ascending-j
// member order, same __fdiv_rn order, same 8-wide fmaf cc chain, same
// 128-thread tree. The only change is structural: the masked 100-iteration
// scan is replaced by a ballot-compacted ascending-j member list, so the
// accumulation is a tight branch-free cnt-iteration loop (full MLP).
// Grid (20, 16, 4).
// ---------------------------------------------------------------------------
__global__ __launch_bounds__(128) void k_update() {
    const int k  = blockIdx.x;
    const int b  = blockIdx.y;
    const int ch = blockIdx.z;
    const int tid = threadIdx.x;

    __shared__ float ccs[KCL];
    __shared__ int   labs[KSEL];
    __shared__ int   list[KSEL];
    __shared__ int   s_cnt;
    __shared__ float red[128];

    if (tid < KCL) {
        const float4 v = reinterpret_cast<const float4*>(g_ccpart)[b * KCL + tid];
        ccs[tid] = ((v.x + v.y) + v.z) + v.w;    // fixed chunk order 0,1,2,3
    }
    __syncthreads();

    if (tid < KSEL) {
        const float xx = g_xx[b * PROWS + tid];
        const float4* dotp = reinterpret_cast<const float4*>(g_dot) +
                             (size_t)(b * PROWS + tid) * KCL;
        const float4 v0 = dotp[0];
        float bv = (xx - 2.0f * (((v0.x + v0.y) + v0.z) + v0.w)) + ccs[0];
        int best = 0;
#pragma unroll
        for (int k2 = 1; k2 < KCL; ++k2) {
            const float4 v = dotp[k2];
            const float d2 = (xx - 2.0f * (((v.x + v.y) + v.z) + v.w)) + ccs[k2];
            if (d2 < bv) { bv = d2; best = k2; }   // first-min, like jnp.argmin
        }
        labs[tid] = best;
    }
    __syncthreads();

    // warp 0: compact ascending-j member list (deterministic; int-only, no FP)
    if (tid < 32) {
        int base = 0;
#pragma unroll
        for (int j0 = 0; j0 < KSEL; j0 += 32) {
            const int j = j0 + tid;
            const bool m = (j < KSEL) && (labs[j] == k);
            const unsigned bal = __ballot_sync(0xffffffffu, m);
            if (m) list[base + __popc(bal & ((1u << tid) - 1u))] = j;
            base += __popc(bal);
        }
        if (tid == 0) s_cnt = base;
    }
    __syncthreads();
    const int cnt = s_cnt;

    // accumulate members in ascending j — per-component FP chains identical
    // to the R11 masked loop (a0 from row[tid], a1 from row[tid+128])
    float4 a0 = make_float4(0.f, 0.f, 0.f, 0.f);
    float4 a1 = make_float4(0.f, 0.f, 0.f, 0.f);
    const float4* Xc4 = reinterpret_cast<const float4*>(g_X) +
                        (size_t)b * PROWS * (DTOT / 4) + ch * CHF4;
    for (int i = 0; i < cnt; ++i) {
        const float4* row = Xc4 + (size_t)list[i] * (DTOT / 4);
        const float4 v0 = row[tid];
        const float4 v1 = row[tid + 128];
        a0.x += v0.x; a0.y += v0.y; a0.z += v0.z; a0.w += v0.w;
        a1.x += v1.x; a1.y += v1.y; a1.z += v1.z; a1.w += v1.w;
    }

    if (cnt > 0) {                         // uniform across block
        const float fc = (float)cnt;
        float4 c0, c1;
        c0.x = __fdiv_rn(a0.x, fc); c0.y = __fdiv_rn(a0.y, fc);
        c0.z = __fdiv_rn(a0.z, fc); c0.w = __fdiv_rn(a0.w, fc);
        c1.x = __fdiv_rn(a1.x, fc); c1.y = __fdiv_rn(a1.y, fc);
        c1.z = __fdiv_rn(a1.z, fc); c1.w = __fdiv_rn(a1.w, fc);

        float4* crow = reinterpret_cast<float4*>(g_C) +
                       (size_t)(b * KCL + k) * (DTOT / 4) + ch * CHF4;
        crow[tid] = c0;
        crow[tid + 128] = c1;

        // EXACT R11 cc chain: v0 outer, v1 inner, innermost c1.w*c1.w
        float sq = fmaf(c0.x, c0.x, fmaf(c0.y, c0.y, fmaf(c0.z, c0.z, fmaf(c0.w, c0.w,
                   fmaf(c1.x, c1.x, fmaf(c1.y, c1.y, fmaf(c1.z, c1.z, c1.w * c1.w)))))));
        red[tid] = sq;
        __syncthreads();
        for (int s = 64; s > 0; s >>= 1) {
            if (tid < s) red[tid] += red[tid + s];
            __syncthreads();
        }
        if (tid == 0) g_ccpart[(b * KCL + k) * NCH + ch] = red[0];
    }
}

// ---------------------------------------------------------------------------
// Kernel 5: final part 1, d-chunked, with final label assignment FUSED in
// (passing R12). Grid (16, 4), 64 threads.
// ---------------------------------------------------------------------------
__global__ __launch_bounds__(64) void k_final1() {
    const int b  = blockIdx.x;
    const int ch = blockIdx.y;
    const int tid = threadIdx.x;           // 0..63, float4 column within chunk

    __shared__ float4 seg[KCL][64];
    __shared__ int    labs[KSEL];
    __shared__ float  cnts[KCL];
    __shared__ float  red[64];
    __shared__ float  ccs[KCL];

    if (tid < KCL) {
        const float4 v = reinterpret_cast<const float4*>(g_ccpart)[b * KCL + tid];
        ccs[tid] = ((v.x + v.y) + v.z) + v.w;
    }
#pragma unroll
    for (int k = 0; k < KCL; ++k) seg[k][tid] = make_float4(0.f, 0.f, 0.f, 0.f);
    __syncthreads();

    for (int j = tid; j < KSEL; j += 64) {
        const float xx = g_xx[b * PROWS + j];
        const float4* dotp = reinterpret_cast<const float4*>(g_dot) +
                             (size_t)(b * PROWS + j) * KCL;
        const float4 v0 = dotp[0];
        float bv = (xx - 2.0f * (((v0.x + v0.y) + v0.z) + v0.w)) + ccs[0];
        int best = 0;
#pragma unroll
        for (int k2 = 1; k2 < KCL; ++k2) {
            const float4 v = dotp[k2];
            const float d2 = (xx - 2.0f * (((v.x + v.y) + v.z) + v.w)) + ccs[k2];
            if (d2 < bv) { bv = d2; best = k2; }
        }
        labs[j] = best;
    }
    __syncthreads();

    if (tid < KCL) {
        int c = 0;
        for (int j = 0; j < KSEL; ++j) c += (labs[j] == tid);
        cnts[tid] = (float)c;
    }
    __syncthreads();

    const float4* Xb4 = reinterpret_cast<const float4*>(g_X) + (size_t)b * PROWS * (DTOT / 4);
    const int fi = ch * 64 + tid;          // float4 index within a layer block (0..255)

    for (int j = 0; j < KSEL; ++j) {
        const int lab = labs[j];
        const float4* row = Xb4 + (size_t)j * (DTOT / 4);
        const float4 v0 = row[fi];
        const float4 v1 = row[256 + fi];
        const float4 v2 = row[512 + fi];
        const float4 v3 = row[768 + fi];
        float4 a;
        a.x = (((v0.x + v1.x) + v2.x) + v3.x) * 0.25f;
        a.y = (((v0.y + v1.y) + v2.y) + v3.y) * 0.25f;
        a.z = (((v0.z + v1.z) + v2.z) + v3.z) * 0.25f;
        a.w = (((v0.w + v1.w) + v2.w) + v3.w) * 0.25f;
        float4 s = seg[lab][tid];
        s.x += a.x; s.y += a.y; s.z += a.z; s.w += a.w;
        seg[lab][tid] = s;
    }
    __syncthreads();

    float mx = 0.f, my = 0.f, mz = 0.f, mw = 0.f;
#pragma unroll
    for (int k = 0; k < KCL; ++k) {
        const float fc = cnts[k];
        if (fc > 0.f) {
            const float4 s = seg[k][tid];
            mx += __fdiv_rn(s.x, fc);
            my += __fdiv_rn(s.y, fc);
            mz += __fdiv_rn(s.z, fc);
            mw += __fdiv_rn(s.w, fc);
        }
    }
    const float cx = __fdiv_rn(mx, 20.f);
    const float cy = __fdiv_rn(my, 20.f);
    const float cz = __fdiv_rn(mz, 20.f);
    const float cw = __fdiv_rn(mw, 20.f);

    float4 o; o.x = cx; o.y = cy; o.z = cz; o.w = cw;
    reinterpret_cast<float4*>(g_m)[b * 256 + fi] = o;

    red[tid] = ((cx * cx + cy * cy) + cz * cz) + cw * cw;
    __syncthreads();
    for (int s = 32; s > 0; s >>= 1) {
        if (tid < s) red[tid] += red[tid + s];
        __syncthreads();
    }
    if (tid == 0) g_ns[b * NCH + ch] = red[0];
}

// ---------------------------------------------------------------------------
// Kernel 6: final part 2 — normalize. Grid 16, 256 threads.
// ---------------------------------------------------------------------------
__global__ __launch_bounds__(256) void k_final2(float* __restrict__ out) {
    const int b = blockIdx.x;
    const int tid = threadIdx.x;           // one float4 of D=1024

    const float4 nsv = reinterpret_cast<const float4*>(g_ns)[b];
    const float ns = ((nsv.x + nsv.y) + nsv.z) + nsv.w;
    float norm = __fsqrt_rn(ns);
    norm = fmaxf(norm, 1e-12f);

    const float4 c = reinterpret_cast<const float4*>(g_m)[b * 256 + tid];
    float4 o;
    o.x = __fdiv_rn(c.x, norm);
    o.y = __fdiv_rn(c.y, norm);
    o.z = __fdiv_rn(c.z, norm);
    o.w = __fdiv_rn(c.w, norm);
    reinterpret_cast<float4*>(out)[b * 256 + tid] = o;
}

// ---------------------------------------------------------------------------
// Launch: 25-node dependent chain on the capture stream.
// ---------------------------------------------------------------------------
extern "C" void kernel_launch(void* const* d_in, const int* in_sizes, int n_in,
                              void* d_out, int out_size) {
    (void)in_sizes; (void)n_in; (void)out_size;
    const float* pt = (const float*)d_in[0];   // patch_tokens [4,16,4096,1024] f32
    const float* an = (const float*)d_in[1];   // anomaly_maps [4,16,4096,2] f32
    float* out = (float*)d_out;                // [16,1024] f32

    k_topk  <<<BNUM, 1024>>>(an);
    k_gather<<<dim3(PROWS, BNUM), 128>>>(pt);   // gather + centroid init fused
    for (int it = 0; it < ITERS; ++it) {
        k_assign_part<<<dim3(9, BNUM, NCH), 240>>>();
        k_update     <<<dim3(KCL, BNUM, NCH), 128>>>();
    }
    k_assign_part<<<dim3(9, BNUM, NCH), 240>>>();
    k_final1     <<<dim3(BNUM, NCH), 64>>>();   // final labels + segment means
    k_final2     <<<BNUM, 256>>>(out);
}

// round 15
// speedup vs baseline: 1.2870x; 1.0346x over previous
#include <cuda_runtime.h>
#include <cstdint>
#include <cstring>

// Problem constants (fixed by the dataset)
#define LNUM 4
#define BNUM 16
#define NTOK 4096
#define DDIM 1024
#define KSEL 100
#define KCL  20
#define DTOT 4096   /* LNUM*DDIM */
#define PROWS 112   /* 100 padded to 112 (9 blocks * 12 points + slack) */
#define NCH   4     /* d-chunks for assign/update split */
#define CHF4  256   /* float4 per chunk (1024 floats) */
#define ITERS 10

// ---------------------------------------------------------------------------
// Scratch (static __device__ globals; no allocation anywhere)
// ---------------------------------------------------------------------------
__device__ float g_X    [BNUM * PROWS * DTOT];       // stacked tokens [B][112][4096]
__device__ float g_xx   [BNUM * PROWS];              // |x|^2 per row (full-d)
__device__ float g_C    [BNUM * KCL * DTOT];         // centroids [B][20][4096]
__device__ float g_ccpart[BNUM * KCL * NCH];         // per-chunk partial |c|^2
__device__ float g_dot  [BNUM * PROWS * KCL * NCH];  // per-chunk partial dots
__device__ int   g_top  [BNUM * KSEL];               // top-100 token indices
__device__ float g_m    [BNUM * DDIM];               // pre-normalize centers
__device__ float g_ns   [BNUM * NCH];                // partial sum-of-squares

// floor(linspace(0,99,20)) computed exactly as jnp does it
__constant__ int c_init_idx[KCL] = {0,5,10,15,20,26,31,36,41,46,52,57,62,67,72,78,83,88,93,99};

// ---------------------------------------------------------------------------
// Kernel 1: anomaly score + stable top-100 (bitonic sort). Unchanged (passing).
// ---------------------------------------------------------------------------
__global__ __launch_bounds__(1024) void k_topk(const float* __restrict__ anom) {
    const int b = blockIdx.x;
    const int tid = threadIdx.x;
    __shared__ unsigned long long keys[NTOK];

    for (int n = tid; n < NTOK; n += 1024) {
        float s0 = 0.f, s1 = 0.f;
#pragma unroll
        for (int l = 0; l < LNUM; ++l) {
            const float2 v = reinterpret_cast<const float2*>(anom)[(size_t)(l * BNUM + b) * NTOK + n];
            s0 += v.x;
            s1 += v.y;
        }
        const float m0 = s0 * 0.25f;
        const float m1 = s1 * 0.25f;
        const float mx = fmaxf(m0, m1);
        const float e0 = expf(m0 - mx);
        const float e1 = expf(m1 - mx);
        const float sc = __fdiv_rn(e1, e0 + e1);
        unsigned u = __float_as_uint(sc);
        u = (u & 0x80000000u) ? ~u : (u | 0x80000000u);
        keys[n] = ((unsigned long long)(~u) << 32) | (unsigned)n;
    }

    for (int kk = 2; kk <= NTOK; kk <<= 1) {
        for (int j = kk >> 1; j > 0; j >>= 1) {
            __syncthreads();
            for (int t = tid; t < NTOK; t += 1024) {
                const int ixj = t ^ j;
                if (ixj > t) {
                    const unsigned long long A = keys[t];
                    const unsigned long long Bv = keys[ixj];
                    const bool up = ((t & kk) == 0);
                    if ((A > Bv) == up) { keys[t] = Bv; keys[ixj] = A; }
                }
            }
        }
    }
    __syncthreads();
    if (tid < KSEL) g_top[b * KSEL + tid] = (int)(keys[tid] & 0xFFFFu);
}

// ---------------------------------------------------------------------------
// Kernel 2: gather top tokens + xx, with centroid init FUSED in (passing R12,
// bitwise identical to separate k_init). Grid (112, 16), 128 threads.
// ---------------------------------------------------------------------------
__global__ __launch_bounds__(128) void k_gather(const float* __restrict__ pt) {
    const int j = blockIdx.x;
    const int b = blockIdx.y;
    const int tid = threadIdx.x;
    float* dst = g_X + ((size_t)b * PROWS + j) * DTOT;
    float sq = 0.f;
    __shared__ float red[128];

    bool isInit = false;
    int kc = 0;
    if (j < KSEL) {
#pragma unroll
        for (int k = 0; k < KCL; ++k)
            if (c_init_idx[k] == j) { isInit = true; kc = k; }
    }

    if (j < KSEL) {
        const int idx = g_top[b * KSEL + j];
#pragma unroll
        for (int l = 0; l < LNUM; ++l) {
            const float4* src = reinterpret_cast<const float4*>(
                pt + (((size_t)l * BNUM + b) * NTOK + idx) * DDIM);
            float4* d4 = reinterpret_cast<float4*>(dst + l * DDIM);

            const float4 v0 = src[tid];
            d4[tid] = v0;
            sq = fmaf(v0.x, v0.x, fmaf(v0.y, v0.y, fmaf(v0.z, v0.z, fmaf(v0.w, v0.w, sq))));
            const float4 v1 = src[tid + 128];
            d4[tid + 128] = v1;
            sq = fmaf(v1.x, v1.x, fmaf(v1.y, v1.y, fmaf(v1.z, v1.z, fmaf(v1.w, v1.w, sq))));

            if (isInit) {   // block-uniform branch (j is per-block)
                float4* cd = reinterpret_cast<float4*>(
                    g_C + ((size_t)b * KCL + kc) * DTOT + l * DDIM);
                cd[tid] = v0;
                cd[tid + 128] = v1;
                const float sql =
                    fmaf(v0.x, v0.x, fmaf(v0.y, v0.y, fmaf(v0.z, v0.z, fmaf(v0.w, v0.w,
                    fmaf(v1.x, v1.x, fmaf(v1.y, v1.y, fmaf(v1.z, v1.z, v1.w * v1.w)))))));
                red[tid] = sql;
                __syncthreads();
                for (int s = 64; s > 0; s >>= 1) {
                    if (tid < s) red[tid] += red[tid + s];
                    __syncthreads();
                }
                if (tid == 0) g_ccpart[(b * KCL + kc) * NCH + l] = red[0];
                __syncthreads();
            }
        }
    } else {
        const float4 z = make_float4(0.f, 0.f, 0.f, 0.f);
        float4* d4 = reinterpret_cast<float4*>(dst);
#pragma unroll
        for (int u = 0; u < 8; ++u) d4[tid + u * 128] = z;
    }

    red[tid] = sq;
    __syncthreads();
    for (int s = 64; s > 0; s >>= 1) {
        if (tid < s) red[tid] += red[tid + s];
        __syncthreads();
    }
    if (tid == 0) g_xx[b * PROWS + j] = red[0];
}

// ---------------------------------------------------------------------------
// Kernel 3 (hot, x11): partial dot products — EXACT R11 version (measured
// 16.3us, best). Grid (9, 16, 4) = 576 blocks, 240 threads, 4 blocks/SM.
// ---------------------------------------------------------------------------
__global__ __launch_bounds__(240, 4) void k_assign_part() {
    const int b   = blockIdx.y;
    const int jb  = blockIdx.x * 12;
    const int ch  = blockIdx.z;
    const int tid = threadIdx.x;          // 0..239
    const int ds   = tid & 15;            // d-split slot (16)
    const int tile = tid >> 4;            // 0..14
    const int kg   = tile % 5;            // cluster group (4 clusters)
    const int pg   = tile / 5;            // point group (4 points)

    const float4* Xb4 = reinterpret_cast<const float4*>(g_X) + (size_t)b * PROWS * (DTOT / 4);
    const float4* Cb4 = reinterpret_cast<const float4*>(g_C) + (size_t)b * KCL * (DTOT / 4);

    const float4* xr[4];
    const float4* cr[4];
#pragma unroll
    for (int i = 0; i < 4; ++i)
        xr[i] = Xb4 + (size_t)(jb + pg * 4 + i) * (DTOT / 4) + ch * CHF4;
#pragma unroll
    for (int q = 0; q < 4; ++q)
        cr[q] = Cb4 + (size_t)(kg * 4 + q) * (DTOT / 4) + ch * CHF4;

    float acc[4][4];
#pragma unroll
    for (int i = 0; i < 4; ++i)
#pragma unroll
        for (int q = 0; q < 4; ++q) acc[i][q] = 0.f;

    for (int s = 0; s < 16; ++s) {
        const int f = ds + 16 * s;        // float4 index within chunk (0..255)
        float4 xv[4], cv[4];
#pragma unroll
        for (int i = 0; i < 4; ++i) xv[i] = xr[i][f];
#pragma unroll
        for (int q = 0; q < 4; ++q) cv[q] = cr[q][f];
#pragma unroll
        for (int i = 0; i < 4; ++i)
#pragma unroll
            for (int q = 0; q < 4; ++q) {
                float a = acc[i][q];
                a = fmaf(xv[i].x, cv[q].x, a);
                a = fmaf(xv[i].y, cv[q].y, a);
                a = fmaf(xv[i].z, cv[q].z, a);
                a = fmaf(xv[i].w, cv[q].w, a);
                acc[i][q] = a;
            }
    }

    __shared__ float red[240 * 17];       // padded: slot*17 + ds (conflict-free)
#pragma unroll
    for (int i = 0; i < 4; ++i)
#pragma unroll
        for (int q = 0; q < 4; ++q) {
            const int slot = (pg * 4 + i) * KCL + (kg * 4 + q);
            red[slot * 17 + ds] = acc[i][q];
        }
    __syncthreads();

    {   // one thread per (point,cluster): deterministic fixed-order ds-sum
        const int slot = tid;             // 0..239 = 12*20
        const int p = slot / KCL;
        const int k = slot - p * KCL;
        float ssum = 0.f;
#pragma unroll
        for (int d = 0; d < 16; ++d) ssum += red[slot * 17 + d];
        g_dot[((size_t)(b * PROWS + jb + p) * KCL + k) * NCH + ch] = ssum;
    }
}

// ---------------------------------------------------------------------------
// Kernel 4 (x10): fused label + centroid update. NEW STRUCTURE: the 4 chunk
// blocks of R14 are merged into ONE 512-thread block per (k,b); ch = tid>>7,
// t = tid&127. The argmin + ballot compaction now run ONCE per (k,b) instead
// of 4x (they are integer/FP-identical to R14's). Each chunk's accumulation,
// __fdiv_rn divides, 8-wide fmaf cc chain, and 128-thread tree use EXACTLY
// the operands and order of R14's per-chunk block -> bitwise-identical output.
// Grid (20, 16), 512 threads.
// ---------------------------------------------------------------------------
__global__ __launch_bounds__(512) void k_update() {
    const int k   = blockIdx.x;
    const int b   = blockIdx.y;
    const int tid = threadIdx.x;          // 0..511
    const int ch  = tid >> 7;             // chunk 0..3
    const int t   = tid & 127;            // lane within chunk

    __shared__ float ccs[KCL];
    __shared__ int   labs[KSEL];
    __shared__ int   list[KSEL];
    __shared__ int   s_cnt;
    __shared__ float red[NCH][128];

    if (tid < KCL) {
        const float4 v = reinterpret_cast<const float4*>(g_ccpart)[b * KCL + tid];
        ccs[tid] = ((v.x + v.y) + v.z) + v.w;    // fixed chunk order 0,1,2,3
    }
    __syncthreads();

    if (tid < KSEL) {
        const float xx = g_xx[b * PROWS + tid];
        const float4* dotp = reinterpret_cast<const float4*>(g_dot) +
                             (size_t)(b * PROWS + tid) * KCL;
        const float4 v0 = dotp[0];
        float bv = (xx - 2.0f * (((v0.x + v0.y) + v0.z) + v0.w)) + ccs[0];
        int best = 0;
#pragma unroll
        for (int k2 = 1; k2 < KCL; ++k2) {
            const float4 v = dotp[k2];
            const float d2 = (xx - 2.0f * (((v.x + v.y) + v.z) + v.w)) + ccs[k2];
            if (d2 < bv) { bv = d2; best = k2; }   // first-min, like jnp.argmin
        }
        labs[tid] = best;
    }
    __syncthreads();

    // warp 0: compact ascending-j member list (deterministic; int-only, no FP)
    if (tid < 32) {
        int base = 0;
#pragma unroll
        for (int j0 = 0; j0 < KSEL; j0 += 32) {
            const int j = j0 + tid;
            const bool m = (j < KSEL) && (labs[j] == k);
            const unsigned bal = __ballot_sync(0xffffffffu, m);
            if (m) list[base + __popc(bal & ((1u << tid) - 1u))] = j;
            base += __popc(bal);
        }
        if (tid == 0) s_cnt = base;
    }
    __syncthreads();
    const int cnt = s_cnt;

    // accumulate members in ascending j — per-component FP chains identical
    // to R14 (a0 from row[t], a1 from row[t+128], chunk offset ch*CHF4)
    float4 a0 = make_float4(0.f, 0.f, 0.f, 0.f);
    float4 a1 = make_float4(0.f, 0.f, 0.f, 0.f);
    const float4* Xc4 = reinterpret_cast<const float4*>(g_X) +
                        (size_t)b * PROWS * (DTOT / 4) + ch * CHF4;
    for (int i = 0; i < cnt; ++i) {
        const float4* row = Xc4 + (size_t)list[i] * (DTOT / 4);
        const float4 v0 = row[t];
        const float4 v1 = row[t + 128];
        a0.x += v0.x; a0.y += v0.y; a0.z += v0.z; a0.w += v0.w;
        a1.x += v1.x; a1.y += v1.y; a1.z += v1.z; a1.w += v1.w;
    }

    if (cnt > 0) {                         // uniform across block
        const float fc = (float)cnt;
        float4 c0, c1;
        c0.x = __fdiv_rn(a0.x, fc); c0.y = __fdiv_rn(a0.y, fc);
        c0.z = __fdiv_rn(a0.z, fc); c0.w = __fdiv_rn(a0.w, fc);
        c1.x = __fdiv_rn(a1.x, fc); c1.y = __fdiv_rn(a1.y, fc);
        c1.z = __fdiv_rn(a1.z, fc); c1.w = __fdiv_rn(a1.w, fc);

        float4* crow = reinterpret_cast<float4*>(g_C) +
                       (size_t)(b * KCL + k) * (DTOT / 4) + ch * CHF4;
        crow[t] = c0;
        crow[t + 128] = c1;

        // EXACT R11/R14 cc chain: c0 outer, c1 inner, innermost c1.w*c1.w
        float sq = fmaf(c0.x, c0.x, fmaf(c0.y, c0.y, fmaf(c0.z, c0.z, fmaf(c0.w, c0.w,
                   fmaf(c1.x, c1.x, fmaf(c1.y, c1.y, fmaf(c1.z, c1.z, c1.w * c1.w)))))));
        red[ch][t] = sq;
        __syncthreads();
        for (int s = 64; s > 0; s >>= 1) {
            if (t < s) red[ch][t] += red[ch][t + s];
            __syncthreads();
        }
        if (t == 0) g_ccpart[(b * KCL + k) * NCH + ch] = red[ch][0];
    }
}

// ---------------------------------------------------------------------------
// Kernel 5: final part 1, d-chunked, with final label assignment FUSED in
// (passing R12). Grid (16, 4), 64 threads.
// ---------------------------------------------------------------------------
__global__ __launch_bounds__(64) void k_final1() {
    const int b  = blockIdx.x;
    const int ch = blockIdx.y;
    const int tid = threadIdx.x;           // 0..63, float4 column within chunk

    __shared__ float4 seg[KCL][64];
    __shared__ int    labs[KSEL];
    __shared__ float  cnts[KCL];
    __shared__ float  red[64];
    __shared__ float  ccs[KCL];

    if (tid < KCL) {
        const float4 v = reinterpret_cast<const float4*>(g_ccpart)[b * KCL + tid];
        ccs[tid] = ((v.x + v.y) + v.z) + v.w;
    }
#pragma unroll
    for (int k = 0; k < KCL; ++k) seg[k][tid] = make_float4(0.f, 0.f, 0.f, 0.f);
    __syncthreads();

    for (int j = tid; j < KSEL; j += 64) {
        const float xx = g_xx[b * PROWS + j];
        const float4* dotp = reinterpret_cast<const float4*>(g_dot) +
                             (size_t)(b * PROWS + j) * KCL;
        const float4 v0 = dotp[0];
        float bv = (xx - 2.0f * (((v0.x + v0.y) + v0.z) + v0.w)) + ccs[0];
        int best = 0;
#pragma unroll
        for (int k2 = 1; k2 < KCL; ++k2) {
            const float4 v = dotp[k2];
            const float d2 = (xx - 2.0f * (((v.x + v.y) + v.z) + v.w)) + ccs[k2];
            if (d2 < bv) { bv = d2; best = k2; }
        }
        labs[j] = best;
    }
    __syncthreads();

    if (tid < KCL) {
        int c = 0;
        for (int j = 0; j < KSEL; ++j) c += (labs[j] == tid);
        cnts[tid] = (float)c;
    }
    __syncthreads();

    const float4* Xb4 = reinterpret_cast<const float4*>(g_X) + (size_t)b * PROWS * (DTOT / 4);
    const int fi = ch * 64 + tid;          // float4 index within a layer block (0..255)

    for (int j = 0; j < KSEL; ++j) {
        const int lab = labs[j];
        const float4* row = Xb4 + (size_t)j * (DTOT / 4);
        const float4 v0 = row[fi];
        const float4 v1 = row[256 + fi];
        const float4 v2 = row[512 + fi];
        const float4 v3 = row[768 + fi];
        float4 a;
        a.x = (((v0.x + v1.x) + v2.x) + v3.x) * 0.25f;
        a.y = (((v0.y + v1.y) + v2.y) + v3.y) * 0.25f;
        a.z = (((v0.z + v1.z) + v2.z) + v3.z) * 0.25f;
        a.w = (((v0.w + v1.w) + v2.w) + v3.w) * 0.25f;
        float4 s = seg[lab][tid];
        s.x += a.x; s.y += a.y; s.z += a.z; s.w += a.w;
        seg[lab][tid] = s;
    }
    __syncthreads();

    float mx = 0.f, my = 0.f, mz = 0.f, mw = 0.f;
#pragma unroll
    for (int k = 0; k < KCL; ++k) {
        const float fc = cnts[k];
        if (fc > 0.f) {
            const float4 s = seg[k][tid];
            mx += __fdiv_rn(s.x, fc);
            my += __fdiv_rn(s.y, fc);
            mz += __fdiv_rn(s.z, fc);
            mw += __fdiv_rn(s.w, fc);
        }
    }
    const float cx = __fdiv_rn(mx, 20.f);
    const float cy = __fdiv_rn(my, 20.f);
    const float cz = __fdiv_rn(mz, 20.f);
    const float cw = __fdiv_rn(mw, 20.f);

    float4 o; o.x = cx; o.y = cy; o.z = cz; o.w = cw;
    reinterpret_cast<float4*>(g_m)[b * 256 + fi] = o;

    red[tid] = ((cx * cx + cy * cy) + cz * cz) + cw * cw;
    __syncthreads();
    for (int s = 32; s > 0; s >>= 1) {
        if (tid < s) red[tid] += red[tid + s];
        __syncthreads();
    }
    if (tid == 0) g_ns[b * NCH + ch] = red[0];
}

// ---------------------------------------------------------------------------
// Kernel 6: final part 2 — normalize. Grid 16, 256 threads.
// ---------------------------------------------------------------------------
__global__ __launch_bounds__(256) void k_final2(float* __restrict__ out) {
    const int b = blockIdx.x;
    const int tid = threadIdx.x;           // one float4 of D=1024

    const float4 nsv = reinterpret_cast<const float4*>(g_ns)[b];
    const float ns = ((nsv.x + nsv.y) + nsv.z) + nsv.w;
    float norm = __fsqrt_rn(ns);
    norm = fmaxf(norm, 1e-12f);

    const float4 c = reinterpret_cast<const float4*>(g_m)[b * 256 + tid];
    float4 o;
    o.x = __fdiv_rn(c.x, norm);
    o.y = __fdiv_rn(c.y, norm);
    o.z = __fdiv_rn(c.z, norm);
    o.w = __fdiv_rn(c.w, norm);
    reinterpret_cast<float4*>(out)[b * 256 + tid] = o;
}

// ---------------------------------------------------------------------------
// Launch: 25-node dependent chain on the capture stream.
// ---------------------------------------------------------------------------
extern "C" void kernel_launch(void* const* d_in, const int* in_sizes, int n_in,
                              void* d_out, int out_size) {
    (void)in_sizes; (void)n_in; (void)out_size;
    const float* pt = (const float*)d_in[0];   // patch_tokens [4,16,4096,1024] f32
    const float* an = (const float*)d_in[1];   // anomaly_maps [4,16,4096,2] f32
    float* out = (float*)d_out;                // [16,1024] f32

    k_topk  <<<BNUM, 1024>>>(an);
    k_gather<<<dim3(PROWS, BNUM), 128>>>(pt);   // gather + centroid init fused
    for (int it = 0; it < ITERS; ++it) {
        k_assign_part<<<dim3(9, BNUM, NCH), 240>>>();
        k_update     <<<dim3(KCL, BNUM), 512>>>();
    }
    k_assign_part<<<dim3(9, BNUM, NCH), 240>>>();
    k_final1     <<<dim3(BNUM, NCH), 64>>>();   // final labels + segment means
    k_final2     <<<BNUM, 256>>>(out);
}